// round 14
// baseline (speedup 1.0000x reference)
#include <cuda_runtime.h>
#include <cstdint>

// Problem constants
static constexpr int NB = 16;
static constexpr int NC = 256;
static constexpr int NH = 64;
static constexpr int NW = 64;
static constexpr int NP = 9;
static constexpr int DISP = 4;

// Tiling: TI=2 rows per CTA -> small regs/smem -> 3 CTAs/SM (27 warps)
static constexpr int TI = 2;
static constexpr int CH = 8;
static constexpr int NSTAGE = NC / CH;        // 32
static constexpr int YROWS = TI + 2 * DISP;   // 10
static constexpr int PITCH = 384;
static constexpr int XAREA = CH * TI * PITCH;     // 6144
static constexpr int YAREA = CH * YROWS * PITCH;  // 30720
static constexpr int BUF = XAREA + YAREA;         // 36864
static constexpr int NTHREADS = 288;              // 9 warps, warp = di
static constexpr int NROWS = CH * YROWS + CH * TI; // 80 y + 16 x = 96
static constexpr int STAGE_BYTES = CH * NH * NW * 4; // 131072
static constexpr int ROWB = NW * 4;               // 256B per bulk copy

// smem: full[2] mbarriers at 0,8; buffers at 128
static constexpr int BUF0 = 128;
static constexpr int SMEM_TOTAL = BUF0 + 2 * BUF; // 73856 -> 3 CTAs/SM

// Row skew: alternate rows by 64B so 2-row x 16-jg phases hit 8 distinct
// 16B bank groups.
__device__ __forceinline__ unsigned skew(int r) {
    return (unsigned)((r & 1) << 6);
}
__device__ __forceinline__ void upk(unsigned long long v, float& lo, float& hi) {
    asm("mov.b64 {%0, %1}, %2;" : "=f"(lo), "=f"(hi) : "l"(v));
}
// {lo: a.hi, hi: b.lo}
__device__ __forceinline__ unsigned long long hilo(unsigned long long a,
                                                   unsigned long long b) {
    unsigned long long r;
    asm("{ .reg .b32 al, ah, bl, bh;\n\t"
        "mov.b64 {al, ah}, %1;\n\t"
        "mov.b64 {bl, bh}, %2;\n\t"
        "mov.b64 %0, {ah, bl}; }"
        : "=l"(r) : "l"(a), "l"(b));
    return r;
}
// {lo: a.lo, hi: b.hi}
__device__ __forceinline__ unsigned long long lohi(unsigned long long a,
                                                   unsigned long long b) {
    unsigned long long r;
    asm("{ .reg .b32 al, ah, bl, bh;\n\t"
        "mov.b64 {al, ah}, %1;\n\t"
        "mov.b64 {bl, bh}, %2;\n\t"
        "mov.b64 %0, {al, bh}; }"
        : "=l"(r) : "l"(a), "l"(b));
    return r;
}
__device__ __forceinline__ void fma2(unsigned long long& acc,
                                     unsigned long long a, unsigned long long b) {
    asm("fma.rn.f32x2 %0, %1, %2, %0;" : "+l"(acc) : "l"(a), "l"(b));
}
__device__ __forceinline__ void lds2(unsigned addr,
                                     unsigned long long& a, unsigned long long& b) {
    asm volatile("ld.shared.v2.b64 {%0, %1}, [%2];"
                 : "=l"(a), "=l"(b) : "r"(addr));
}
__device__ __forceinline__ void mbar_init(unsigned addr, unsigned count) {
    asm volatile("mbarrier.init.shared.b64 [%0], %1;" :: "r"(addr), "r"(count) : "memory");
}
__device__ __forceinline__ void mbar_expect(unsigned addr, unsigned bytes) {
    asm volatile("mbarrier.arrive.expect_tx.shared.b64 _, [%0], %1;"
                 :: "r"(addr), "r"(bytes) : "memory");
}
__device__ __forceinline__ void mbar_wait(unsigned addr, unsigned parity) {
    asm volatile(
        "{\n\t"
        ".reg .pred P;\n\t"
        "WL_%=:\n\t"
        "mbarrier.try_wait.parity.acquire.cta.shared::cta.b64 P, [%0], %1, 0x989680;\n\t"
        "@P bra.uni WD_%=;\n\t"
        "bra.uni WL_%=;\n\t"
        "WD_%=:\n\t"
        "}"
        :: "r"(addr), "r"(parity) : "memory");
}
__device__ __forceinline__ void bulk_g2s(unsigned dst, const void* src,
                                         unsigned bytes, unsigned mbar) {
    asm volatile(
        "cp.async.bulk.shared::cta.global.mbarrier::complete_tx::bytes "
        "[%0], [%1], %2, [%3];"
        :: "r"(dst), "l"(src), "r"(bytes), "r"(mbar) : "memory");
}

__global__ void __launch_bounds__(NTHREADS, 3)
corr_kernel(const float* __restrict__ x, const float* __restrict__ y,
            float* __restrict__ out) {
    extern __shared__ char smem[];
    unsigned sm32;
    asm("{ .reg .u64 t; cvta.to.shared.u64 t, %1; cvt.u32.u64 %0, t; }"
        : "=r"(sm32) : "l"(smem));

    const int tid  = threadIdx.x;
    const int di   = tid >> 5;       // warp = displacement row 0..8
    const int lane = tid & 31;
    const int jg   = lane >> 1;      // 0..15 : group of 4 output columns
    const int ti   = lane & 1;       // 0..1  : i-row in tile
    const int i0   = blockIdx.x * TI;
    const int b    = blockIdx.y;

    // Zero both buffers (halo cols / OOB rows stay zero forever).
    for (int o = tid * 16; o < 2 * BUF; o += NTHREADS * 16)
        *reinterpret_cast<float4*>(smem + BUF0 + o) = make_float4(0.f, 0.f, 0.f, 0.f);

    if (tid == 0) {
        mbar_init(sm32 + 0, 1);   // full[0]
        mbar_init(sm32 + 8, 1);   // full[1]
    }
    __syncthreads();
    asm volatile("fence.proxy.async.shared::cta;" ::: "memory");

    // Valid bytes per stage (OOB y rows never copied).
    const int lo = (DISP - i0) > 0 ? (DISP - i0) : 0;
    const int hi = (i0 + TI - 1 + DISP - (NH - 1)) > 0
                   ? (i0 + TI - 1 + DISP - (NH - 1)) : 0;
    const unsigned BYTES = (unsigned)((CH * (YROWS - lo - hi) + CH * TI) * ROWB);

    // Row-owner precompute: thread k < 96 owns row k (one 256B bulk per stage).
    const char* src0 = nullptr;
    unsigned dsto = 0;
    bool valid = false;
    if (tid < NROWS) {
        const int k = tid;
        if (k < CH * YROWS) {
            const int cc = k / YROWS;
            const int rr = k - cc * YROWS;
            const int gy = i0 - DISP + rr;
            valid = ((unsigned)gy < (unsigned)NH);
            if (valid)
                src0 = reinterpret_cast<const char*>(
                    y + (((size_t)(b * NC + cc) * NH + gy) * NW));
            dsto = XAREA + cc * (YROWS * PITCH) + rr * PITCH + skew(rr) + 16;
        } else {
            const int j  = k - CH * YROWS;
            const int cc = j >> 1;
            const int rr = j & 1;
            valid = true;
            src0 = reinterpret_cast<const char*>(
                x + (((size_t)(b * NC + cc) * NH + (i0 + rr)) * NW));
            dsto = cc * (TI * PITCH) + rr * PITCH + skew(rr);
        }
    }

    // Prologue: tid0 registers expected bytes for stages 0,1; owners issue.
    if (tid == 0) {
        mbar_expect(sm32 + 0, BYTES);
        mbar_expect(sm32 + 8, BYTES);
    }
    __syncthreads();   // expects registered before any completion can land
    if (valid) {
        bulk_g2s(sm32 + BUF0 + dsto, src0, ROWB, sm32 + 0);
        bulk_g2s(sm32 + BUF0 + BUF + dsto, src0 + STAGE_BYTES, ROWB, sm32 + 8);
    }

    // Accumulators: even dj -> 2 aligned pairs; odd dj -> 1 mid pair + 1
    // packed border pair (lo = sA = x0*wh, hi = sB = x3*vl).
    unsigned long long accE[5][2], accO[4], accAB[4];
#pragma unroll
    for (int e = 0; e < 5; ++e) { accE[e][0] = 0ull; accE[e][1] = 0ull; }
#pragma unroll
    for (int o = 0; o < 4; ++o) { accO[o] = 0ull; accAB[o] = 0ull; }

    const int r = ti + di;   // y smem row 0..9
    const unsigned xoff = sm32 + BUF0 + (unsigned)(ti * PITCH) + skew(ti) + jg * 16;
    const unsigned yoff = sm32 + BUF0 + (unsigned)XAREA
                        + (unsigned)(r * PITCH) + skew(r) + jg * 16;

    for (int s = 0; s < NSTAGE; ++s) {
        const unsigned mb = sm32 + (unsigned)((s & 1) * 8);
        mbar_wait(mb, (unsigned)((s >> 1) & 1));
        if (tid == 0 && s + 2 < NSTAGE) mbar_expect(mb, BYTES);

        const unsigned bo = (unsigned)((s & 1) * BUF);
#pragma unroll
        for (int cc = 0; cc < CH; ++cc) {
            const unsigned xp = bo + (unsigned)(cc * (TI * PITCH)) + xoff;
            const unsigned yp = bo + (unsigned)(cc * (YROWS * PITCH)) + yoff;

            // X: 4 floats (2 aligned pairs). W: 12 floats (6 aligned pairs),
            // y window = cols jg*4-4 .. jg*4+7 (left pad at yp).
            unsigned long long X[2], W[6];
            lds2(xp, X[0], X[1]);
            lds2(yp,      W[0], W[1]);
            lds2(yp + 16, W[2], W[3]);
            lds2(yp + 32, W[4], W[5]);

            const unsigned long long Sx = hilo(X[0], X[1]);  // (x1, x2)
            const unsigned long long Ax = lohi(X[0], X[1]);  // (x0, x3)

            // Even dj = 2e: pairs (c0,c1)->W[e], (c2,c3)->W[e+1].
#pragma unroll
            for (int e = 0; e < 5; ++e) {
                fma2(accE[e][0], X[0], W[e]);
                fma2(accE[e][1], X[1], W[e + 1]);
            }
            // Odd dj = 2o+1: mid pair (c1,c2)->W[o+1]; packed borders:
            // lo += x0 * W[o].hi (sA), hi += x3 * W[o+2].lo (sB).
#pragma unroll
            for (int o = 0; o < 4; ++o) {
                fma2(accO[o], Sx, W[o + 1]);
                fma2(accAB[o], Ax, hilo(W[o], W[o + 2]));
            }
        }

        __syncthreads();   // everyone finished reading buffer (s&1)
        if (valid && s + 2 < NSTAGE) {
            bulk_g2s(sm32 + BUF0 + (unsigned)((s & 1) * BUF) + dsto,
                     src0 + (size_t)(s + 2) * STAGE_BYTES, ROWB, mb);
        }
    }

    // ---- epilogue: scale by 1/C and store (4 cols per thread) ----
    const float sc = 1.0f / (float)NC;
    float* obase = out + (((size_t)b * (NP * NP) + (size_t)di * NP) * NH
                          + (i0 + ti)) * NW + jg * 4;
#pragma unroll
    for (int e = 0; e < 5; ++e) {          // dj = 2e
        float4 v;
        upk(accE[e][0], v.x, v.y);
        upk(accE[e][1], v.z, v.w);
        v.x *= sc; v.y *= sc; v.z *= sc; v.w *= sc;
        *reinterpret_cast<float4*>(obase + (size_t)(2 * e) * NH * NW) = v;
    }
#pragma unroll
    for (int o = 0; o < 4; ++o) {          // dj = 2o+1
        float f1, f2, sa, sb;
        upk(accO[o], f1, f2);
        upk(accAB[o], sa, sb);
        float4 v;
        v.x = sa * sc; v.y = f1 * sc; v.z = f2 * sc; v.w = sb * sc;
        *reinterpret_cast<float4*>(obase + (size_t)(2 * o + 1) * NH * NW) = v;
    }
}

extern "C" void kernel_launch(void* const* d_in, const int* in_sizes, int n_in,
                              void* d_out, int out_size) {
    const float* x = (const float*)d_in[0];
    const float* y = (const float*)d_in[1];
    float* out = (float*)d_out;
    (void)in_sizes; (void)n_in; (void)out_size;

    cudaFuncSetAttribute(corr_kernel,
                         cudaFuncAttributeMaxDynamicSharedMemorySize, SMEM_TOTAL);

    dim3 grid(NH / TI, NB);   // (32, 16) = 512 blocks, 3 CTAs/SM
    corr_kernel<<<grid, NTHREADS, SMEM_TOTAL>>>(x, y, out);
}

// round 15
// speedup vs baseline: 1.0304x; 1.0304x over previous
#include <cuda_runtime.h>
#include <cstdint>

// Problem constants
static constexpr int NB = 16;
static constexpr int NC = 256;
static constexpr int NH = 64;
static constexpr int NW = 64;
static constexpr int NP = 9;
static constexpr int DISP = 4;

// Tiling: TI=2 rows per CTA -> small regs/smem -> 3 CTAs/SM (27 warps)
static constexpr int TI = 2;
static constexpr int CH = 8;
static constexpr int NSTAGE = NC / CH;        // 32
static constexpr int YROWS = TI + 2 * DISP;   // 10
static constexpr int PITCH = 384;
static constexpr int XAREA = CH * TI * PITCH;     // 6144
static constexpr int YAREA = CH * YROWS * PITCH;  // 30720
static constexpr int BUF = XAREA + YAREA;         // 36864
static constexpr int NTHREADS = 288;              // 9 warps, warp = di
static constexpr int NROWS = CH * YROWS + CH * TI; // 80 y + 16 x = 96
static constexpr int STAGE_BYTES = CH * NH * NW * 4; // 131072
static constexpr int ROWB = NW * 4;               // 256B per bulk copy

// smem: full[2] mbarriers at 0,8; buffers at 128
static constexpr int BUF0 = 128;
static constexpr int SMEM_TOTAL = BUF0 + 2 * BUF; // 73856 -> 3 CTAs/SM

// Row skew: alternate rows by 64B so 2-row x 16-jg phases hit 8 distinct
// 16B bank groups.
__device__ __forceinline__ unsigned skew(int r) {
    return (unsigned)((r & 1) << 6);
}
__device__ __forceinline__ void upk(unsigned long long v, float& lo, float& hi) {
    asm("mov.b64 {%0, %1}, %2;" : "=f"(lo), "=f"(hi) : "l"(v));
}
__device__ __forceinline__ unsigned long long pk(float lo, float hi) {
    unsigned long long r;
    asm("mov.b64 %0, {%1, %2};" : "=l"(r) : "f"(lo), "f"(hi));
    return r;
}
__device__ __forceinline__ void fma2(unsigned long long& acc,
                                     unsigned long long a, unsigned long long b) {
    asm("fma.rn.f32x2 %0, %1, %2, %0;" : "+l"(acc) : "l"(a), "l"(b));
}
__device__ __forceinline__ void lds2(unsigned addr,
                                     unsigned long long& a, unsigned long long& b) {
    asm volatile("ld.shared.v2.b64 {%0, %1}, [%2];"
                 : "=l"(a), "=l"(b) : "r"(addr));
}
__device__ __forceinline__ void mbar_init(unsigned addr, unsigned count) {
    asm volatile("mbarrier.init.shared.b64 [%0], %1;" :: "r"(addr), "r"(count) : "memory");
}
__device__ __forceinline__ void mbar_expect(unsigned addr, unsigned bytes) {
    asm volatile("mbarrier.arrive.expect_tx.shared.b64 _, [%0], %1;"
                 :: "r"(addr), "r"(bytes) : "memory");
}
__device__ __forceinline__ void mbar_wait(unsigned addr, unsigned parity) {
    asm volatile(
        "{\n\t"
        ".reg .pred P;\n\t"
        "WL_%=:\n\t"
        "mbarrier.try_wait.parity.acquire.cta.shared::cta.b64 P, [%0], %1, 0x989680;\n\t"
        "@P bra.uni WD_%=;\n\t"
        "bra.uni WL_%=;\n\t"
        "WD_%=:\n\t"
        "}"
        :: "r"(addr), "r"(parity) : "memory");
}
__device__ __forceinline__ void bulk_g2s(unsigned dst, const void* src,
                                         unsigned bytes, unsigned mbar) {
    asm volatile(
        "cp.async.bulk.shared::cta.global.mbarrier::complete_tx::bytes "
        "[%0], [%1], %2, [%3];"
        :: "r"(dst), "l"(src), "r"(bytes), "r"(mbar) : "memory");
}

__global__ void __launch_bounds__(NTHREADS, 3)
corr_kernel(const float* __restrict__ x, const float* __restrict__ y,
            float* __restrict__ out) {
    extern __shared__ char smem[];
    unsigned sm32;
    asm("{ .reg .u64 t; cvta.to.shared.u64 t, %1; cvt.u32.u64 %0, t; }"
        : "=r"(sm32) : "l"(smem));

    const int tid  = threadIdx.x;
    const int di   = tid >> 5;       // warp = displacement row 0..8
    const int lane = tid & 31;
    const int jg   = lane >> 1;      // 0..15 : group of 4 output columns
    const int ti   = lane & 1;       // 0..1  : i-row in tile
    const int i0   = blockIdx.x * TI;
    const int b    = blockIdx.y;

    // Zero both buffers (halo cols / OOB rows stay zero forever).
    for (int o = tid * 16; o < 2 * BUF; o += NTHREADS * 16)
        *reinterpret_cast<float4*>(smem + BUF0 + o) = make_float4(0.f, 0.f, 0.f, 0.f);

    if (tid == 0) {
        mbar_init(sm32 + 0, 1);   // full[0]
        mbar_init(sm32 + 8, 1);   // full[1]
    }
    __syncthreads();
    asm volatile("fence.proxy.async.shared::cta;" ::: "memory");

    // Valid bytes per stage (OOB y rows never copied).
    const int lo = (DISP - i0) > 0 ? (DISP - i0) : 0;
    const int hi = (i0 + TI - 1 + DISP - (NH - 1)) > 0
                   ? (i0 + TI - 1 + DISP - (NH - 1)) : 0;
    const unsigned BYTES = (unsigned)((CH * (YROWS - lo - hi) + CH * TI) * ROWB);

    // Row-owner precompute: thread k < 96 owns row k (one 256B bulk per stage).
    const char* src0 = nullptr;
    unsigned dsto = 0;
    bool valid = false;
    if (tid < NROWS) {
        const int k = tid;
        if (k < CH * YROWS) {
            const int cc = k / YROWS;
            const int rr = k - cc * YROWS;
            const int gy = i0 - DISP + rr;
            valid = ((unsigned)gy < (unsigned)NH);
            if (valid)
                src0 = reinterpret_cast<const char*>(
                    y + (((size_t)(b * NC + cc) * NH + gy) * NW));
            dsto = XAREA + cc * (YROWS * PITCH) + rr * PITCH + skew(rr) + 16;
        } else {
            const int j  = k - CH * YROWS;
            const int cc = j >> 1;
            const int rr = j & 1;
            valid = true;
            src0 = reinterpret_cast<const char*>(
                x + (((size_t)(b * NC + cc) * NH + (i0 + rr)) * NW));
            dsto = cc * (TI * PITCH) + rr * PITCH + skew(rr);
        }
    }

    // Prologue: tid0 registers expected bytes for stages 0,1; owners issue.
    if (tid == 0) {
        mbar_expect(sm32 + 0, BYTES);
        mbar_expect(sm32 + 8, BYTES);
    }
    __syncthreads();   // expects registered before any completion can land
    if (valid) {
        bulk_g2s(sm32 + BUF0 + dsto, src0, ROWB, sm32 + 0);
        bulk_g2s(sm32 + BUF0 + BUF + dsto, src0 + STAGE_BYTES, ROWB, sm32 + 8);
    }

    // Accumulators: even dj -> 2 aligned col pairs each; odd dj -> 1 mid pair
    // + 2 scalar borders each.
    unsigned long long accE[5][2], accO[4];
    float sA[4], sB[4];
#pragma unroll
    for (int e = 0; e < 5; ++e) { accE[e][0] = 0ull; accE[e][1] = 0ull; }
#pragma unroll
    for (int o = 0; o < 4; ++o) { accO[o] = 0ull; sA[o] = 0.f; sB[o] = 0.f; }

    const int r = ti + di;   // y smem row 0..9
    const unsigned xoff = sm32 + BUF0 + (unsigned)(ti * PITCH) + skew(ti) + jg * 16;
    const unsigned yoff = sm32 + BUF0 + (unsigned)XAREA
                        + (unsigned)(r * PITCH) + skew(r) + jg * 16;

    for (int s = 0; s < NSTAGE; ++s) {
        const unsigned mb = sm32 + (unsigned)((s & 1) * 8);
        mbar_wait(mb, (unsigned)((s >> 1) & 1));
        if (tid == 0 && s + 2 < NSTAGE) mbar_expect(mb, BYTES);

        const unsigned bo = (unsigned)((s & 1) * BUF);
        // FULL unroll: all smem addresses become base + immediate (kills the
        // per-channel IMAD/IADD address arithmetic that showed up as alu%).
#pragma unroll
        for (int cc = 0; cc < CH; ++cc) {
            const unsigned xp = bo + (unsigned)(cc * (TI * PITCH)) + xoff;
            const unsigned yp = bo + (unsigned)(cc * (YROWS * PITCH)) + yoff;

            // X: 4 floats (2 aligned pairs). W: 12 floats (6 aligned pairs),
            // y window = cols jg*4-4 .. jg*4+7 (left pad at yp).
            unsigned long long X[2], W[6];
            lds2(xp, X[0], X[1]);
            lds2(yp,      W[0], W[1]);
            lds2(yp + 16, W[2], W[3]);
            lds2(yp + 32, W[4], W[5]);

            float x0, x1, x2, x3;
            upk(X[0], x0, x1); upk(X[1], x2, x3);
            const unsigned long long Sx = pk(x1, x2);

            // Even dj = 2e: pairs (c0,c1)->W[e], (c2,c3)->W[e+1].
#pragma unroll
            for (int e = 0; e < 5; ++e) {
                fma2(accE[e][0], X[0], W[e]);
                fma2(accE[e][1], X[1], W[e + 1]);
            }
            // Odd dj = 2o+1: mid pair (c1,c2)->W[o+1]; borders c0, c3.
#pragma unroll
            for (int o = 0; o < 4; ++o) {
                fma2(accO[o], Sx, W[o + 1]);
                float wl, wh, vl, vh;
                upk(W[o], wl, wh);        // wh = window float 2o+1
                upk(W[o + 2], vl, vh);    // vl = window float 2o+4
                sA[o] = fmaf(x0, wh, sA[o]);
                sB[o] = fmaf(x3, vl, sB[o]);
            }
        }

        __syncthreads();   // everyone finished reading buffer (s&1)
        if (valid && s + 2 < NSTAGE) {
            bulk_g2s(sm32 + BUF0 + (unsigned)((s & 1) * BUF) + dsto,
                     src0 + (size_t)(s + 2) * STAGE_BYTES, ROWB, mb);
        }
    }

    // ---- epilogue: scale by 1/C and store (4 cols per thread) ----
    const float sc = 1.0f / (float)NC;
    float* obase = out + (((size_t)b * (NP * NP) + (size_t)di * NP) * NH
                          + (i0 + ti)) * NW + jg * 4;
#pragma unroll
    for (int e = 0; e < 5; ++e) {          // dj = 2e
        float4 v;
        upk(accE[e][0], v.x, v.y);
        upk(accE[e][1], v.z, v.w);
        v.x *= sc; v.y *= sc; v.z *= sc; v.w *= sc;
        *reinterpret_cast<float4*>(obase + (size_t)(2 * e) * NH * NW) = v;
    }
#pragma unroll
    for (int o = 0; o < 4; ++o) {          // dj = 2o+1
        float f1, f2;
        upk(accO[o], f1, f2);
        float4 v;
        v.x = sA[o] * sc; v.y = f1 * sc; v.z = f2 * sc; v.w = sB[o] * sc;
        *reinterpret_cast<float4*>(obase + (size_t)(2 * o + 1) * NH * NW) = v;
    }
}

extern "C" void kernel_launch(void* const* d_in, const int* in_sizes, int n_in,
                              void* d_out, int out_size) {
    const float* x = (const float*)d_in[0];
    const float* y = (const float*)d_in[1];
    float* out = (float*)d_out;
    (void)in_sizes; (void)n_in; (void)out_size;

    cudaFuncSetAttribute(corr_kernel,
                         cudaFuncAttributeMaxDynamicSharedMemorySize, SMEM_TOTAL);

    dim3 grid(NH / TI, NB);   // (32, 16) = 512 blocks, 3 CTAs/SM
    corr_kernel<<<grid, NTHREADS, SMEM_TOTAL>>>(x, y, out);
}

// round 16
// speedup vs baseline: 1.2232x; 1.1871x over previous
#include <cuda_runtime.h>
#include <cstdint>

// Problem constants
static constexpr int NB = 16;
static constexpr int NC = 256;
static constexpr int NH = 64;
static constexpr int NW = 64;
static constexpr int NP = 9;
static constexpr int DISP = 4;

// Tiling: TI=2 rows per CTA -> small regs/smem -> 3 CTAs/SM (27 warps)
static constexpr int TI = 2;
static constexpr int CH = 8;
static constexpr int YROWS = TI + 2 * DISP;   // 10
static constexpr int PITCH = 384;
static constexpr int XAREA = CH * TI * PITCH;     // 6144
static constexpr int YAREA = CH * YROWS * PITCH;  // 30720
static constexpr int BUF = XAREA + YAREA;         // 36864
static constexpr int NTHREADS = 288;              // 9 warps, warp = di
static constexpr int NROWS = CH * YROWS + CH * TI; // 80 y + 16 x = 96
static constexpr int STAGE_BYTES = CH * NH * NW * 4; // 131072
static constexpr int ROWB = NW * 4;               // 256B per bulk copy

// smem: full[2] mbarriers at 0,8; buffers at 128
static constexpr int BUF0 = 128;
static constexpr int SMEM_TOTAL = BUF0 + 2 * BUF; // 73856 -> 3 CTAs/SM

// Wave-tail split: 444 full units fill one resident wave (3/SM x 148);
// the last 68 units are computed by 136 half-channel CTAs with RED output.
static constexpr int NFULL = 444;
static constexpr int NUNITS = 512;                 // 32 i-tiles x 16 batches
static constexpr int NTAIL = NUNITS - NFULL;       // 68

__device__ __forceinline__ unsigned skew(int r) {
    return (unsigned)((r & 1) << 6);
}
__device__ __forceinline__ void upk(unsigned long long v, float& lo, float& hi) {
    asm("mov.b64 {%0, %1}, %2;" : "=f"(lo), "=f"(hi) : "l"(v));
}
__device__ __forceinline__ unsigned long long pk(float lo, float hi) {
    unsigned long long r;
    asm("mov.b64 %0, {%1, %2};" : "=l"(r) : "f"(lo), "f"(hi));
    return r;
}
__device__ __forceinline__ void fma2(unsigned long long& acc,
                                     unsigned long long a, unsigned long long b) {
    asm("fma.rn.f32x2 %0, %1, %2, %0;" : "+l"(acc) : "l"(a), "l"(b));
}
__device__ __forceinline__ void lds2(unsigned addr,
                                     unsigned long long& a, unsigned long long& b) {
    asm volatile("ld.shared.v2.b64 {%0, %1}, [%2];"
                 : "=l"(a), "=l"(b) : "r"(addr));
}
__device__ __forceinline__ void mbar_init(unsigned addr, unsigned count) {
    asm volatile("mbarrier.init.shared.b64 [%0], %1;" :: "r"(addr), "r"(count) : "memory");
}
__device__ __forceinline__ void mbar_expect(unsigned addr, unsigned bytes) {
    asm volatile("mbarrier.arrive.expect_tx.shared.b64 _, [%0], %1;"
                 :: "r"(addr), "r"(bytes) : "memory");
}
__device__ __forceinline__ void mbar_wait(unsigned addr, unsigned parity) {
    asm volatile(
        "{\n\t"
        ".reg .pred P;\n\t"
        "WL_%=:\n\t"
        "mbarrier.try_wait.parity.acquire.cta.shared::cta.b64 P, [%0], %1, 0x989680;\n\t"
        "@P bra.uni WD_%=;\n\t"
        "bra.uni WL_%=;\n\t"
        "WD_%=:\n\t"
        "}"
        :: "r"(addr), "r"(parity) : "memory");
}
__device__ __forceinline__ void bulk_g2s(unsigned dst, const void* src,
                                         unsigned bytes, unsigned mbar) {
    asm volatile(
        "cp.async.bulk.shared::cta.global.mbarrier::complete_tx::bytes "
        "[%0], [%1], %2, [%3];"
        :: "r"(dst), "l"(src), "r"(bytes), "r"(mbar) : "memory");
}
__device__ __forceinline__ void redadd(float* p, float v) {
    asm volatile("red.global.add.f32 [%0], %1;" :: "l"(p), "f"(v) : "memory");
}

// Pre-kernel: zero the 68 tail units' output tiles (RED targets).
__global__ void zero_tail(float* __restrict__ out) {
    const int u  = NFULL + blockIdx.x;     // 444..511
    const int b  = u >> 5;
    const int it = u & 31;
    float* base = out + (((size_t)b * (NP * NP)) * NH + it * TI) * NW;
    for (int k = threadIdx.x; k < NP * NP * (TI * NW / 4); k += blockDim.x) {
        const int dj = k >> 5;             // 32 float4 per dj (2 rows x 64 cols)
        const int q  = k & 31;
        *reinterpret_cast<float4*>(base + (size_t)dj * NH * NW + q * 4) =
            make_float4(0.f, 0.f, 0.f, 0.f);
    }
}

__global__ void __launch_bounds__(NTHREADS, 3)
corr_kernel(const float* __restrict__ x, const float* __restrict__ y,
            float* __restrict__ out) {
    extern __shared__ char smem[];
    unsigned sm32;
    asm("{ .reg .u64 t; cvta.to.shared.u64 t, %1; cvt.u32.u64 %0, t; }"
        : "=r"(sm32) : "l"(smem));

    const int tid  = threadIdx.x;
    const int di   = tid >> 5;       // warp = displacement row 0..8
    const int lane = tid & 31;
    const int jg   = lane >> 1;      // 0..15 : group of 4 output columns
    const int ti   = lane & 1;       // 0..1  : i-row in tile

    // Work mapping: bids 0..443 = full units (32 stages, STG epilogue).
    // bids 444..579 = 68 tail units x 2 channel-halves (16 stages, RED).
    const int bid = blockIdx.x;
    int u, ns, cbase;
    bool full;
    if (bid < NFULL) { u = bid; ns = 32; cbase = 0; full = true; }
    else {
        const int t = bid - NFULL;
        u = NFULL + (t >> 1);
        ns = 16;
        cbase = (t & 1) * (NC / 2);
        full = false;
    }
    const int b  = u >> 5;
    const int i0 = (u & 31) * TI;

    // Zero both buffers (halo cols / OOB rows stay zero forever).
    for (int o = tid * 16; o < 2 * BUF; o += NTHREADS * 16)
        *reinterpret_cast<float4*>(smem + BUF0 + o) = make_float4(0.f, 0.f, 0.f, 0.f);

    if (tid == 0) {
        mbar_init(sm32 + 0, 1);   // full[0]
        mbar_init(sm32 + 8, 1);   // full[1]
    }
    __syncthreads();
    asm volatile("fence.proxy.async.shared::cta;" ::: "memory");

    // Valid bytes per stage (OOB y rows never copied).
    const int lo = (DISP - i0) > 0 ? (DISP - i0) : 0;
    const int hi = (i0 + TI - 1 + DISP - (NH - 1)) > 0
                   ? (i0 + TI - 1 + DISP - (NH - 1)) : 0;
    const unsigned BYTES = (unsigned)((CH * (YROWS - lo - hi) + CH * TI) * ROWB);

    // Row-owner precompute: thread k < 96 owns row k (one 256B bulk per stage).
    const char* src0 = nullptr;
    unsigned dsto = 0;
    bool valid = false;
    if (tid < NROWS) {
        const int k = tid;
        if (k < CH * YROWS) {
            const int cc = k / YROWS;
            const int rr = k - cc * YROWS;
            const int gy = i0 - DISP + rr;
            valid = ((unsigned)gy < (unsigned)NH);
            if (valid)
                src0 = reinterpret_cast<const char*>(
                    y + (((size_t)(b * NC + cbase + cc) * NH + gy) * NW));
            dsto = XAREA + cc * (YROWS * PITCH) + rr * PITCH + skew(rr) + 16;
        } else {
            const int j  = k - CH * YROWS;
            const int cc = j >> 1;
            const int rr = j & 1;
            valid = true;
            src0 = reinterpret_cast<const char*>(
                x + (((size_t)(b * NC + cbase + cc) * NH + (i0 + rr)) * NW));
            dsto = cc * (TI * PITCH) + rr * PITCH + skew(rr);
        }
    }

    // Prologue: tid0 registers expected bytes for stages 0,1; owners issue.
    if (tid == 0) {
        mbar_expect(sm32 + 0, BYTES);
        mbar_expect(sm32 + 8, BYTES);
    }
    __syncthreads();   // expects registered before any completion can land
    if (valid) {
        bulk_g2s(sm32 + BUF0 + dsto, src0, ROWB, sm32 + 0);
        bulk_g2s(sm32 + BUF0 + BUF + dsto, src0 + STAGE_BYTES, ROWB, sm32 + 8);
    }

    // Accumulators: even dj -> 2 aligned col pairs each; odd dj -> 1 mid pair
    // + 2 scalar borders each.
    unsigned long long accE[5][2], accO[4];
    float sA[4], sB[4];
#pragma unroll
    for (int e = 0; e < 5; ++e) { accE[e][0] = 0ull; accE[e][1] = 0ull; }
#pragma unroll
    for (int o = 0; o < 4; ++o) { accO[o] = 0ull; sA[o] = 0.f; sB[o] = 0.f; }

    const int r = ti + di;   // y smem row 0..9
    const unsigned xoff = sm32 + BUF0 + (unsigned)(ti * PITCH) + skew(ti) + jg * 16;
    const unsigned yoff = sm32 + BUF0 + (unsigned)XAREA
                        + (unsigned)(r * PITCH) + skew(r) + jg * 16;

    for (int s = 0; s < ns; ++s) {
        const unsigned mb = sm32 + (unsigned)((s & 1) * 8);
        mbar_wait(mb, (unsigned)((s >> 1) & 1));
        if (tid == 0 && s + 2 < ns) mbar_expect(mb, BYTES);

        const unsigned bo = (unsigned)((s & 1) * BUF);
#pragma unroll 2
        for (int cc = 0; cc < CH; ++cc) {
            const unsigned xp = bo + (unsigned)(cc * (TI * PITCH)) + xoff;
            const unsigned yp = bo + (unsigned)(cc * (YROWS * PITCH)) + yoff;

            // X: 4 floats (2 aligned pairs). W: 12 floats (6 aligned pairs),
            // y window = cols jg*4-4 .. jg*4+7 (left pad at yp).
            unsigned long long X[2], W[6];
            lds2(xp, X[0], X[1]);
            lds2(yp,      W[0], W[1]);
            lds2(yp + 16, W[2], W[3]);
            lds2(yp + 32, W[4], W[5]);

            float x0, x1, x2, x3;
            upk(X[0], x0, x1); upk(X[1], x2, x3);
            const unsigned long long Sx = pk(x1, x2);

            // Even dj = 2e: pairs (c0,c1)->W[e], (c2,c3)->W[e+1].
#pragma unroll
            for (int e = 0; e < 5; ++e) {
                fma2(accE[e][0], X[0], W[e]);
                fma2(accE[e][1], X[1], W[e + 1]);
            }
            // Odd dj = 2o+1: mid pair (c1,c2)->W[o+1]; borders c0, c3.
#pragma unroll
            for (int o = 0; o < 4; ++o) {
                fma2(accO[o], Sx, W[o + 1]);
                float wl, wh, vl, vh;
                upk(W[o], wl, wh);        // wh = window float 2o+1
                upk(W[o + 2], vl, vh);    // vl = window float 2o+4
                sA[o] = fmaf(x0, wh, sA[o]);
                sB[o] = fmaf(x3, vl, sB[o]);
            }
        }

        __syncthreads();   // everyone finished reading buffer (s&1)
        if (valid && s + 2 < ns) {
            bulk_g2s(sm32 + BUF0 + (unsigned)((s & 1) * BUF) + dsto,
                     src0 + (size_t)(s + 2) * STAGE_BYTES, ROWB, mb);
        }
    }

    // ---- epilogue: scale by 1/C; full units store, tail halves RED-add ----
    const float sc = 1.0f / (float)NC;
    float* obase = out + (((size_t)b * (NP * NP) + (size_t)di * NP) * NH
                          + (i0 + ti)) * NW + jg * 4;
    if (full) {
#pragma unroll
        for (int e = 0; e < 5; ++e) {          // dj = 2e
            float4 v;
            upk(accE[e][0], v.x, v.y);
            upk(accE[e][1], v.z, v.w);
            v.x *= sc; v.y *= sc; v.z *= sc; v.w *= sc;
            *reinterpret_cast<float4*>(obase + (size_t)(2 * e) * NH * NW) = v;
        }
#pragma unroll
        for (int o = 0; o < 4; ++o) {          // dj = 2o+1
            float f1, f2;
            upk(accO[o], f1, f2);
            float4 v;
            v.x = sA[o] * sc; v.y = f1 * sc; v.z = f2 * sc; v.w = sB[o] * sc;
            *reinterpret_cast<float4*>(obase + (size_t)(2 * o + 1) * NH * NW) = v;
        }
    } else {
        // Two CTAs contribute per element: exactly two atomic f32 adds onto a
        // zeroed tile -> a+b, order-independent -> deterministic.
#pragma unroll
        for (int e = 0; e < 5; ++e) {
            float* op = obase + (size_t)(2 * e) * NH * NW;
            float f0, f1, f2, f3;
            upk(accE[e][0], f0, f1);
            upk(accE[e][1], f2, f3);
            redadd(op + 0, f0 * sc); redadd(op + 1, f1 * sc);
            redadd(op + 2, f2 * sc); redadd(op + 3, f3 * sc);
        }
#pragma unroll
        for (int o = 0; o < 4; ++o) {
            float* op = obase + (size_t)(2 * o + 1) * NH * NW;
            float f1, f2;
            upk(accO[o], f1, f2);
            redadd(op + 0, sA[o] * sc); redadd(op + 1, f1 * sc);
            redadd(op + 2, f2 * sc);    redadd(op + 3, sB[o] * sc);
        }
    }
}

extern "C" void kernel_launch(void* const* d_in, const int* in_sizes, int n_in,
                              void* d_out, int out_size) {
    const float* x = (const float*)d_in[0];
    const float* y = (const float*)d_in[1];
    float* out = (float*)d_out;
    (void)in_sizes; (void)n_in; (void)out_size;

    cudaFuncSetAttribute(corr_kernel,
                         cudaFuncAttributeMaxDynamicSharedMemorySize, SMEM_TOTAL);

    // 1) zero the 68 tail tiles (RED targets), 2) 444 full CTAs + 136 tail
    // half-CTAs: the fulls fill exactly one resident wave (3/SM x 148).
    zero_tail<<<NTAIL, 256>>>(out);
    corr_kernel<<<NFULL + 2 * NTAIL, NTHREADS, SMEM_TOTAL>>>(x, y, out);
}